// round 4
// baseline (speedup 1.0000x reference)
#include <cuda_runtime.h>

// Problem constants (fixed by the reference)
#define NB  16
#define NC  512
#define NK  512
#define NHW 4096   // 64*64

// Allocation-free scratch: transposed centers (C-major -> [c][k]) and ||c_k||^2
__device__ float g_centT[NC * NK];
__device__ float g_csq[NK];

// ---------------------------------------------------------------------------
// Prep: transpose centers to (C, K) for coalesced B-tile loads; c_sq in fp64.
// ---------------------------------------------------------------------------
__global__ void prep_kernel(const float* __restrict__ cent) {
    int idx = blockIdx.x * blockDim.x + threadIdx.x;
    if (idx < NC * NK) {
        int k = idx / NC;
        int c = idx % NC;           // consecutive threads read consecutive c: coalesced
        g_centT[c * NK + k] = cent[k * NC + c];
    }
    if (idx < NK) {
        double s = 0.0;
        for (int c = 0; c < NC; ++c) {
            double v = (double)cent[idx * NC + c];
            s += v * v;
        }
        g_csq[idx] = (float)s;
    }
}

// ---------------------------------------------------------------------------
// Packed fp32x2 helpers (FFMA2 — PTX-only, doubles fp32 FMA throughput)
// ---------------------------------------------------------------------------
__device__ __forceinline__ void ffma2(unsigned long long& d,
                                      unsigned long long a,
                                      unsigned long long b) {
    asm("fma.rn.f32x2 %0, %1, %2, %0;" : "+l"(d) : "l"(a), "l"(b));
}

__device__ __forceinline__ unsigned long long dup2(float v) {
    unsigned long long r;
    asm("mov.b64 %0, {%1, %1};" : "=l"(r) : "f"(v));
    return r;
}

__device__ __forceinline__ float2 unpk2(unsigned long long v) {
    float2 r;
    asm("mov.b64 {%0, %1}, %2;" : "=f"(r.x), "=f"(r.y) : "l"(v));
    return r;
}

// Monotonic (float, k) -> u64 key. Smaller distance -> smaller key;
// ties -> smaller k (matches jnp.argmin first-occurrence semantics).
__device__ __forceinline__ unsigned long long enc_key(float v, int k) {
    unsigned u = __float_as_uint(v);
    u = (u & 0x80000000u) ? ~u : (u | 0x80000000u);
    return ((unsigned long long)u << 32) | (unsigned)k;
}

// ---------------------------------------------------------------------------
// Main kernel: block = 128 pixels x all 512 codes (4 k-chunks of 128).
// 256 threads, 8x8 micro-tile per thread, TILE_C = 8, fused argmin epilogue.
// ---------------------------------------------------------------------------
__global__ __launch_bounds__(256, 2)
void codebook_argmin(const float* __restrict__ x, float* __restrict__ out) {
    const int bx = blockIdx.x;          // 512 blocks
    const int b  = bx >> 5;             // batch
    const int p0 = (bx & 31) << 7;      // pixel tile start within batch (128 pixels)
    const float* xb = x + (size_t)b * NC * NHW + p0;

    __shared__ __align__(16) float xs[8][128];   // [c][pixel]
    __shared__ __align__(16) float cs[8][128];   // [c][k]
    __shared__ unsigned long long best[128];

    const int tid = threadIdx.x;
    const int tx  = tid & 15;           // k direction (16)
    const int ty  = tid >> 4;           // pixel direction (16)

    if (tid < 128) best[tid] = 0xFFFFFFFFFFFFFFFFULL;

    // tile-load addressing: each thread loads one float4 of x and one of centT
    const int lr = tid >> 5;            // c row within chunk (0..7)
    const int lp = (tid & 31) << 2;     // column (0..124)
    const float* xg = xb + (size_t)lr * NHW + lp;
    const float* cg = g_centT + lr * NK + lp;

    #pragma unroll 1
    for (int kc = 0; kc < 4; ++kc) {
        const int k0 = kc << 7;

        unsigned long long acc[8][4];   // [pixel][k-pair]
        #pragma unroll
        for (int i = 0; i < 8; ++i)
            #pragma unroll
            for (int j = 0; j < 4; ++j) acc[i][j] = 0ULL;

        #pragma unroll 1
        for (int c0 = 0; c0 < NC; c0 += 8) {
            float4 xv = *reinterpret_cast<const float4*>(xg + (size_t)c0 * NHW);
            float4 cv = *reinterpret_cast<const float4*>(cg + c0 * NK + k0);
            __syncthreads();            // protect previous tile reads
            *reinterpret_cast<float4*>(&xs[lr][lp]) = xv;
            *reinterpret_cast<float4*>(&cs[lr][lp]) = cv;
            __syncthreads();

            #pragma unroll
            for (int cc = 0; cc < 8; ++cc) {
                float4 a0 = *reinterpret_cast<const float4*>(&xs[cc][ty * 8]);
                float4 a1 = *reinterpret_cast<const float4*>(&xs[cc][ty * 8 + 4]);
                ulonglong2 b0 = *reinterpret_cast<const ulonglong2*>(&cs[cc][tx * 4]);
                ulonglong2 b1 = *reinterpret_cast<const ulonglong2*>(&cs[cc][64 + tx * 4]);
                float av[8] = {a0.x, a0.y, a0.z, a0.w, a1.x, a1.y, a1.z, a1.w};
                #pragma unroll
                for (int i = 0; i < 8; ++i) {
                    unsigned long long ap = dup2(av[i]);
                    ffma2(acc[i][0], ap, b0.x);
                    ffma2(acc[i][1], ap, b0.y);
                    ffma2(acc[i][2], ap, b1.x);
                    ffma2(acc[i][3], ap, b1.y);
                }
            }
        }

        // Epilogue: dist = c_sq[k] - 2*dot (x_sq is per-pixel constant -> dropped)
        #pragma unroll
        for (int i = 0; i < 8; ++i) {
            unsigned long long bl = 0xFFFFFFFFFFFFFFFFULL;
            #pragma unroll
            for (int j = 0; j < 4; ++j) {
                int kb = k0 + ((j < 2) ? (tx * 4 + j * 2)
                                       : (64 + tx * 4 + (j - 2) * 2));
                float2 d = unpk2(acc[i][j]);
                float v0 = fmaf(-2.0f, d.x, g_csq[kb]);
                float v1 = fmaf(-2.0f, d.y, g_csq[kb + 1]);
                unsigned long long e0 = enc_key(v0, kb);
                unsigned long long e1 = enc_key(v1, kb + 1);
                unsigned long long m  = e0 < e1 ? e0 : e1;
                if (m < bl) bl = m;
            }
            atomicMin(&best[ty * 8 + i], bl);
        }
    }

    __syncthreads();
    if (tid < 128) {
        // Output dtype is float32: write the argmin index as a float value.
        out[(size_t)b * NHW + p0 + tid] =
            (float)(int)(unsigned)(best[tid] & 0xFFFFFFFFULL);
    }
}

// ---------------------------------------------------------------------------
// Launch
// ---------------------------------------------------------------------------
extern "C" void kernel_launch(void* const* d_in, const int* in_sizes, int n_in,
                              void* d_out, int out_size) {
    const float* x    = (const float*)d_in[0];
    const float* cent = (const float*)d_in[1];
    // Defensive: x has 33.5M elements, centers 262144 — keep the big one as x.
    if (n_in >= 2 && in_sizes[0] < in_sizes[1]) {
        const float* t = x; x = cent; cent = t;
    }

    prep_kernel<<<(NC * NK + 255) / 256, 256>>>(cent);
    codebook_argmin<<<NB * 32, 256>>>(x, (float*)d_out);
    (void)out_size;
}

// round 6
// speedup vs baseline: 1.6471x; 1.6471x over previous
#include <cuda_runtime.h>
#include <cuda_fp16.h>
#include <mma.h>
#include <cstdint>

using namespace nvcuda;

#define NB  16
#define NC  512
#define NK  512
#define NHW 4096
#define NP  (NB * NHW)   // 65536 pixels

// --------------------------------------------------------------------------
// Allocation-free scratch: center limbs + ||c||^2
// --------------------------------------------------------------------------
__device__ __half g_ch[NK * NC];
__device__ __half g_cl[NK * NC];
__device__ float  g_csq[NK];

// --------------------------------------------------------------------------
// Prep: centers -> fp16 hi/lo limbs ([k][c] row-major) + fp64-accurate csq
// --------------------------------------------------------------------------
__global__ void convert_c(const float* __restrict__ cent) {
    int idx = blockIdx.x * 256 + threadIdx.x;
    if (idx < NK * NC) {
        float f   = cent[idx];
        __half hi = __float2half_rn(f);
        g_ch[idx] = hi;
        g_cl[idx] = __float2half_rn(f - __half2float(hi));
    }
    if (idx < NK) {
        double s = 0.0;
        for (int c = 0; c < NC; ++c) {
            double v = (double)cent[idx * NC + c];
            s += v * v;
        }
        g_csq[idx] = (float)s;
    }
}

// --------------------------------------------------------------------------
// Helpers
// --------------------------------------------------------------------------
__device__ __forceinline__ uint32_t smem_u32(const void* p) {
    uint32_t a;
    asm("{ .reg .u64 t; cvta.to.shared.u64 t, %1; cvt.u32.u64 %0, t; }"
        : "=r"(a) : "l"(p));
    return a;
}

// Monotonic (float, k) -> u64 key; smaller distance -> smaller key; ties -> smaller k.
__device__ __forceinline__ unsigned long long enc_key(float v, int k) {
    unsigned u = __float_as_uint(v);
    u = (u & 0x80000000u) ? ~u : (u | 0x80000000u);
    return ((unsigned long long)u << 32) | (unsigned)k;
}

__device__ __forceinline__ uint32_t pack_hi2(float a, float b) {
    __half2 h = __halves2half2(__float2half_rn(a), __float2half_rn(b));
    return *reinterpret_cast<uint32_t*>(&h);
}
__device__ __forceinline__ uint32_t pack_lo2(float a, float b) {
    float ra = a - __half2float(__float2half_rn(a));
    float rb = b - __half2float(__float2half_rn(b));
    __half2 h = __halves2half2(__float2half_rn(ra), __float2half_rn(rb));
    return *reinterpret_cast<uint32_t*>(&h);
}

// --------------------------------------------------------------------------
// Smem layout (bytes)
//   A limbs (col-major [px + ch*136], 32 ch/stage): 2 limbs x 8704 x 2 stages
//   B limbs (col-major [ch + code*40], 128 codes) : 2 limbs x 10240 x 2 stages
//   EPI 128x128 fp32, CSQ 512 fp32, BEST 128 u64
// --------------------------------------------------------------------------
#define A_LIMB   8704
#define A_STG    17408
#define B_LIMB   10240
#define B_STG    20480
#define OFF_A    0
#define OFF_B    34816
#define OFF_EPI  75776
#define OFF_CSQ  141312
#define OFF_BEST 143360
#define SMEM_TOTAL 144384

// --------------------------------------------------------------------------
// Main kernel: 2-limb fp16 HMMA GEMM + fused argmin.
// CTA: 128 pixels x (4 chunks of 128 codes). 64 flat iterations of 32-ch
// tiles, double-buffered (LDG+convert prefetch for A, cp.async for B).
// --------------------------------------------------------------------------
__global__ __launch_bounds__(256, 1)
void hmma_argmin(const float* __restrict__ x, float* __restrict__ out) {
    extern __shared__ __align__(1024) char smem[];
    const uint32_t sb = smem_u32(smem);
    const int tid = threadIdx.x;
    const int wid = tid >> 5;
    const int wm  = wid >> 2;      // 0..1 : 64-pixel row block
    const int wn  = wid & 3;       // 0..3 : 32-code col block

    const int p0  = blockIdx.x * 128;
    const int b   = p0 >> 12;
    const int hw0 = p0 & 4095;
    const float* xb = x + (size_t)b * NC * NHW + hw0;

    unsigned long long* best = (unsigned long long*)(smem + OFF_BEST);
    float* cs = (float*)(smem + OFF_CSQ);
    if (tid < 128) best[tid] = ~0ULL;
    cs[tid]       = g_csq[tid];
    cs[tid + 256] = g_csq[tid + 256];

    // x-tile thread mapping: 32 ch x 128 px, each thread 16 px of one ch
    const int lch = tid >> 3;            // 0..31
    const int lpx = (tid & 7) << 4;      // 0,16,...,112

    float4 xr[4];
    auto ldg_x = [&](int i) {
        const int c0 = (i & 15) << 5;
        const float* src = xb + (size_t)(c0 + lch) * NHW + lpx;
        xr[0] = *(const float4*)(src);
        xr[1] = *(const float4*)(src + 4);
        xr[2] = *(const float4*)(src + 8);
        xr[3] = *(const float4*)(src + 12);
    };

    auto sts_a = [&](int stg) {
        char* ph = smem + OFF_A + stg * A_STG + lch * 272 + lpx * 2;
        float f[16] = { xr[0].x, xr[0].y, xr[0].z, xr[0].w,
                        xr[1].x, xr[1].y, xr[1].z, xr[1].w,
                        xr[2].x, xr[2].y, xr[2].z, xr[2].w,
                        xr[3].x, xr[3].y, xr[3].z, xr[3].w };
        uint4 H0 = { pack_hi2(f[0],  f[1]),  pack_hi2(f[2],  f[3]),
                     pack_hi2(f[4],  f[5]),  pack_hi2(f[6],  f[7]) };
        uint4 H1 = { pack_hi2(f[8],  f[9]),  pack_hi2(f[10], f[11]),
                     pack_hi2(f[12], f[13]), pack_hi2(f[14], f[15]) };
        uint4 L0 = { pack_lo2(f[0],  f[1]),  pack_lo2(f[2],  f[3]),
                     pack_lo2(f[4],  f[5]),  pack_lo2(f[6],  f[7]) };
        uint4 L1 = { pack_lo2(f[8],  f[9]),  pack_lo2(f[10], f[11]),
                     pack_lo2(f[12], f[13]), pack_lo2(f[14], f[15]) };
        *(uint4*)(ph)               = H0;
        *(uint4*)(ph + 16)          = H1;
        *(uint4*)(ph + A_LIMB)      = L0;
        *(uint4*)(ph + A_LIMB + 16) = L1;
    };

    auto cpa_b = [&](int i, int stg) {
        const int kc = i >> 4;
        const int c0 = (i & 15) << 5;
        #pragma unroll
        for (int u = 0; u < 4; ++u) {
            int q    = tid + (u << 8);          // 0..1023
            int limb = q >> 9;
            int n    = (q >> 2) & 127;
            int seg  = q & 3;
            const __half* src = (limb ? g_cl : g_ch)
                                + (size_t)(kc * 128 + n) * NC + c0 + seg * 8;
            uint32_t dst = sb + OFF_B + stg * B_STG + limb * B_LIMB
                           + n * 80 + seg * 16;
            asm volatile("cp.async.cg.shared.global [%0], [%1], 16;"
                         :: "r"(dst), "l"(src) : "memory");
        }
        asm volatile("cp.async.commit_group;" ::: "memory");
    };

    wmma::fragment<wmma::accumulator, 16, 16, 16, float> acc[4][2];
    #pragma unroll
    for (int m = 0; m < 4; ++m)
        #pragma unroll
        for (int n = 0; n < 2; ++n) wmma::fill_fragment(acc[m][n], 0.0f);

    auto compute = [&](int stg) {
        const __half* Ah = (const __half*)(smem + OFF_A + stg * A_STG);
        const __half* Al = (const __half*)((const char*)Ah + A_LIMB);
        const __half* Bh = (const __half*)(smem + OFF_B + stg * B_STG);
        const __half* Bl = (const __half*)((const char*)Bh + B_LIMB);
        #pragma unroll
        for (int ks = 0; ks < 2; ++ks) {
            wmma::fragment<wmma::matrix_a, 16, 16, 16, __half, wmma::col_major> ah[4], al[4];
            #pragma unroll
            for (int m = 0; m < 4; ++m) {
                const int ro = wm * 64 + m * 16 + ks * 16 * 136;
                wmma::load_matrix_sync(ah[m], Ah + ro, 136);
                wmma::load_matrix_sync(al[m], Al + ro, 136);
            }
            #pragma unroll
            for (int n = 0; n < 2; ++n) {
                wmma::fragment<wmma::matrix_b, 16, 16, 16, __half, wmma::col_major> bh, bl;
                const int co = (wn * 32 + n * 16) * 40 + ks * 16;
                wmma::load_matrix_sync(bh, Bh + co, 40);
                wmma::load_matrix_sync(bl, Bl + co, 40);
                #pragma unroll
                for (int m = 0; m < 4; ++m) {
                    wmma::mma_sync(acc[m][n], ah[m], bh, acc[m][n]);
                    wmma::mma_sync(acc[m][n], ah[m], bl, acc[m][n]);
                    wmma::mma_sync(acc[m][n], al[m], bh, acc[m][n]);
                }
            }
        }
    };

    auto epilogue = [&](int kc) {
        float* epi = (float*)(smem + OFF_EPI);
        #pragma unroll
        for (int m = 0; m < 4; ++m)
            #pragma unroll
            for (int n = 0; n < 2; ++n) {
                wmma::store_matrix_sync(epi + (wm * 64 + m * 16) * 128
                                            + wn * 32 + n * 16,
                                        acc[m][n], 128, wmma::mem_row_major);
                wmma::fill_fragment(acc[m][n], 0.0f);
            }
        __syncthreads();
        const int row = tid >> 1, half = tid & 1;
        const float* er = epi + row * 128 + half * 64;
        unsigned long long bl = ~0ULL;
        #pragma unroll 8
        for (int j = 0; j < 64; ++j) {
            int kg = kc * 128 + half * 64 + j;
            float v = fmaf(-2.0f, er[j], cs[kg]);
            unsigned long long e = enc_key(v, kg);
            if (e < bl) bl = e;
        }
        atomicMin(&best[row], bl);
        __syncthreads();
    };

    // ---- prologue: prime stage 0, prefetch x for iter 1 ----
    ldg_x(0);
    __syncthreads();
    sts_a(0);
    cpa_b(0, 0);
    ldg_x(1);
    asm volatile("cp.async.wait_group 0;" ::: "memory");
    __syncthreads();

    #pragma unroll 1
    for (int i = 0; i < 64; ++i) {
        const int cur = i & 1, nxt = cur ^ 1;
        if (i + 1 < 64) {
            sts_a(nxt);            // xr holds data for iter i+1
            cpa_b(i + 1, nxt);
            if (i + 2 < 64) ldg_x(i + 2);
        }
        compute(cur);
        if ((i & 15) == 15) epilogue(i >> 4);
        if (i + 1 < 64) asm volatile("cp.async.wait_group 0;" ::: "memory");
        __syncthreads();
    }

    if (tid < 128) {
        out[(size_t)p0 + tid] =
            (float)(int)(unsigned)(best[tid] & 0xFFFFFFFFULL);
    }
}

// --------------------------------------------------------------------------
// Launch
// --------------------------------------------------------------------------
extern "C" void kernel_launch(void* const* d_in, const int* in_sizes, int n_in,
                              void* d_out, int out_size) {
    const float* x    = (const float*)d_in[0];
    const float* cent = (const float*)d_in[1];
    if (n_in >= 2 && in_sizes[0] < in_sizes[1]) {
        const float* t = x; x = cent; cent = t;
    }

    cudaFuncSetAttribute(hmma_argmin,
                         cudaFuncAttributeMaxDynamicSharedMemorySize, SMEM_TOTAL);

    convert_c<<<(NK * NC + 255) / 256, 256>>>(cent);
    hmma_argmin<<<NP / 128, 256, SMEM_TOTAL>>>(x, (float*)d_out);
    (void)out_size;
}

// round 7
// speedup vs baseline: 2.3538x; 1.4291x over previous
#include <cuda_runtime.h>
#include <cuda_fp16.h>
#include <mma.h>
#include <cstdint>

using namespace nvcuda;

#define NB  16
#define NC  512
#define NK  512
#define NHW 4096
#define NP  (NB * NHW)   // 65536 pixels

// --------------------------------------------------------------------------
// Allocation-free scratch
// --------------------------------------------------------------------------
__device__ __half g_ch[NK * NC];                 // centers hi-limb [k][c]
__device__ __half g_cl[NK * NC];                 // centers lo-limb
__device__ float  g_csq[NK];                     // ||c_k||^2 (fp64-accumulated)
__device__ unsigned long long g_part[(size_t)NP * 4];  // per-(pixel,chunk) min keys

// --------------------------------------------------------------------------
// Prep kernels
// --------------------------------------------------------------------------
__global__ void convert_c(const float* __restrict__ cent) {
    int idx = blockIdx.x * 256 + threadIdx.x;
    if (idx < NK * NC) {
        float f   = cent[idx];
        __half hi = __float2half_rn(f);
        g_ch[idx] = hi;
        g_cl[idx] = __float2half_rn(f - __half2float(hi));
    }
}

// one block per code k: 128 threads, fp64 tree reduction
__global__ void csq_kernel(const float* __restrict__ cent) {
    __shared__ double red[128];
    const int k = blockIdx.x;
    const int t = threadIdx.x;
    double s = 0.0;
    #pragma unroll
    for (int i = 0; i < 4; ++i) {
        double v = (double)cent[k * NC + t + i * 128];
        s += v * v;
    }
    red[t] = s;
    __syncthreads();
    for (int off = 64; off > 0; off >>= 1) {
        if (t < off) red[t] += red[t + off];
        __syncthreads();
    }
    if (t == 0) g_csq[k] = (float)red[0];
}

// --------------------------------------------------------------------------
// Helpers
// --------------------------------------------------------------------------
__device__ __forceinline__ uint32_t smem_u32(const void* p) {
    uint32_t a;
    asm("{ .reg .u64 t; cvta.to.shared.u64 t, %1; cvt.u32.u64 %0, t; }"
        : "=r"(a) : "l"(p));
    return a;
}
__device__ __forceinline__ unsigned long long enc_key(float v, int k) {
    unsigned u = __float_as_uint(v);
    u = (u & 0x80000000u) ? ~u : (u | 0x80000000u);
    return ((unsigned long long)u << 32) | (unsigned)k;
}
__device__ __forceinline__ uint32_t pack_hi2(float a, float b) {
    __half2 h = __halves2half2(__float2half_rn(a), __float2half_rn(b));
    return *reinterpret_cast<uint32_t*>(&h);
}
__device__ __forceinline__ uint32_t pack_lo2(float a, float b) {
    float ra = a - __half2float(__float2half_rn(a));
    float rb = b - __half2float(__float2half_rn(b));
    __half2 h = __halves2half2(__float2half_rn(ra), __float2half_rn(rb));
    return *reinterpret_cast<uint32_t*>(&h);
}

// --------------------------------------------------------------------------
// Smem layout (bytes).  EPI (64 KB) overlays A+B after the mainloop.
//   A: col-major [px + ch*136] halves, 32 ch/stage, 2 limbs x 2 stages
//   B: col-major [ch + code*40] halves, 128 codes,  2 limbs x 2 stages
// --------------------------------------------------------------------------
#define A_LIMB   8704
#define A_STG    17408
#define B_LIMB   10240
#define B_STG    20480
#define OFF_A    0
#define OFF_B    34816
#define OFF_CSQ  75776
#define SMEM_TOTAL 76288

// --------------------------------------------------------------------------
// Main kernel: CTA = 128 pixels x 128 codes, 16 K-iters of 32 channels.
// 2 CTAs/SM (regs capped at 128). Double-buffered A (LDG+convert) + B
// (cp.async). Single fused epilogue -> per-chunk min key to g_part.
// --------------------------------------------------------------------------
__global__ __launch_bounds__(256, 2)
void hmma_argmin(const float* __restrict__ x) {
    extern __shared__ __align__(1024) char smem[];
    const uint32_t sb = smem_u32(smem);
    const int tid = threadIdx.x;
    const int wid = tid >> 5;
    const int wm  = wid >> 2;      // 0..1 : 64-pixel block
    const int wn  = wid & 3;       // 0..3 : 32-code block

    const int grp = blockIdx.x >> 2;     // pixel group (0..511)
    const int kc  = blockIdx.x & 3;      // code chunk (0..3)
    const int p0  = grp * 128;
    const int b   = p0 >> 12;
    const int hw0 = p0 & 4095;
    const float* xb = x + (size_t)b * NC * NHW + hw0;

    float* cs = (float*)(smem + OFF_CSQ);
    if (tid < 128) cs[tid] = g_csq[kc * 128 + tid];

    // x-tile mapping: 32 ch x 128 px; each thread 16 px of one ch
    const int lch = tid >> 3;
    const int lpx = (tid & 7) << 4;

    float4 xr[4];
    auto ldg_x = [&](int i) {
        const float* src = xb + (size_t)((i << 5) + lch) * NHW + lpx;
        xr[0] = *(const float4*)(src);
        xr[1] = *(const float4*)(src + 4);
        xr[2] = *(const float4*)(src + 8);
        xr[3] = *(const float4*)(src + 12);
    };

    auto sts_a = [&](int stg) {
        char* ph = smem + OFF_A + stg * A_STG + lch * 272 + lpx * 2;
        float f[16] = { xr[0].x, xr[0].y, xr[0].z, xr[0].w,
                        xr[1].x, xr[1].y, xr[1].z, xr[1].w,
                        xr[2].x, xr[2].y, xr[2].z, xr[2].w,
                        xr[3].x, xr[3].y, xr[3].z, xr[3].w };
        uint4 H0 = { pack_hi2(f[0],  f[1]),  pack_hi2(f[2],  f[3]),
                     pack_hi2(f[4],  f[5]),  pack_hi2(f[6],  f[7]) };
        uint4 H1 = { pack_hi2(f[8],  f[9]),  pack_hi2(f[10], f[11]),
                     pack_hi2(f[12], f[13]), pack_hi2(f[14], f[15]) };
        uint4 L0 = { pack_lo2(f[0],  f[1]),  pack_lo2(f[2],  f[3]),
                     pack_lo2(f[4],  f[5]),  pack_lo2(f[6],  f[7]) };
        uint4 L1 = { pack_lo2(f[8],  f[9]),  pack_lo2(f[10], f[11]),
                     pack_lo2(f[12], f[13]), pack_lo2(f[14], f[15]) };
        *(uint4*)(ph)               = H0;
        *(uint4*)(ph + 16)          = H1;
        *(uint4*)(ph + A_LIMB)      = L0;
        *(uint4*)(ph + A_LIMB + 16) = L1;
    };

    auto cpa_b = [&](int i, int stg) {
        const int c0 = i << 5;
        #pragma unroll
        for (int u = 0; u < 4; ++u) {
            int q    = tid + (u << 8);          // 0..1023
            int limb = q >> 9;
            int n    = (q >> 2) & 127;
            int seg  = q & 3;
            const __half* src = (limb ? g_cl : g_ch)
                                + (size_t)(kc * 128 + n) * NC + c0 + seg * 8;
            uint32_t dst = sb + OFF_B + stg * B_STG + limb * B_LIMB
                           + n * 80 + seg * 16;
            asm volatile("cp.async.cg.shared.global [%0], [%1], 16;"
                         :: "r"(dst), "l"(src) : "memory");
        }
        asm volatile("cp.async.commit_group;" ::: "memory");
    };

    wmma::fragment<wmma::accumulator, 16, 16, 16, float> acc[4][2];
    #pragma unroll
    for (int m = 0; m < 4; ++m)
        #pragma unroll
        for (int n = 0; n < 2; ++n) wmma::fill_fragment(acc[m][n], 0.0f);

    // B fragments hoisted per k-step; A loaded transiently per m (reg cap)
    auto compute = [&](int stg) {
        const __half* Ah = (const __half*)(smem + OFF_A + stg * A_STG);
        const __half* Al = (const __half*)((const char*)Ah + A_LIMB);
        const __half* Bh = (const __half*)(smem + OFF_B + stg * B_STG);
        const __half* Bl = (const __half*)((const char*)Bh + B_LIMB);
        #pragma unroll
        for (int ks = 0; ks < 2; ++ks) {
            wmma::fragment<wmma::matrix_b, 16, 16, 16, __half, wmma::col_major> bh[2], bl[2];
            #pragma unroll
            for (int n = 0; n < 2; ++n) {
                const int co = (wn * 32 + n * 16) * 40 + ks * 16;
                wmma::load_matrix_sync(bh[n], Bh + co, 40);
                wmma::load_matrix_sync(bl[n], Bl + co, 40);
            }
            #pragma unroll
            for (int m = 0; m < 4; ++m) {
                wmma::fragment<wmma::matrix_a, 16, 16, 16, __half, wmma::col_major> ah, al;
                const int ro = wm * 64 + m * 16 + ks * 16 * 136;
                wmma::load_matrix_sync(ah, Ah + ro, 136);
                wmma::load_matrix_sync(al, Al + ro, 136);
                #pragma unroll
                for (int n = 0; n < 2; ++n) {
                    wmma::mma_sync(acc[m][n], ah, bh[n], acc[m][n]);
                    wmma::mma_sync(acc[m][n], ah, bl[n], acc[m][n]);
                    wmma::mma_sync(acc[m][n], al, bh[n], acc[m][n]);
                }
            }
        }
    };

    // ---- prologue ----
    ldg_x(0);
    __syncthreads();
    sts_a(0);
    cpa_b(0, 0);
    ldg_x(1);
    asm volatile("cp.async.wait_group 0;" ::: "memory");
    __syncthreads();

    #pragma unroll 1
    for (int i = 0; i < 16; ++i) {
        const int cur = i & 1, nxt = cur ^ 1;
        if (i + 1 < 16) {
            sts_a(nxt);            // xr holds data for iter i+1
            cpa_b(i + 1, nxt);
            if (i + 2 < 16) ldg_x(i + 2);
        }
        compute(cur);
        if (i + 1 < 16) asm volatile("cp.async.wait_group 0;" ::: "memory");
        __syncthreads();
    }

    // ---- epilogue (EPI overlays A/B; all smem reads done, synced above) ----
    float* epi = (float*)smem;
    #pragma unroll
    for (int m = 0; m < 4; ++m)
        #pragma unroll
        for (int n = 0; n < 2; ++n)
            wmma::store_matrix_sync(epi + (wm * 64 + m * 16) * 128
                                        + wn * 32 + n * 16,
                                    acc[m][n], 128, wmma::mem_row_major);
    __syncthreads();

    const int row  = tid >> 1;
    const int half = tid & 1;
    const float* er = epi + row * 128 + half * 64;
    unsigned long long bl = ~0ULL;
    #pragma unroll 8
    for (int j = 0; j < 64; ++j) {
        int kg  = kc * 128 + half * 64 + j;
        float v = fmaf(-2.0f, er[j], cs[half * 64 + j]);
        unsigned long long e = enc_key(v, kg);
        if (e < bl) bl = e;
    }
    unsigned long long other = __shfl_xor_sync(0xFFFFFFFFu, bl, 1);
    if (other < bl) bl = other;
    if (half == 0)
        g_part[(size_t)(p0 + row) * 4 + kc] = bl;
}

// --------------------------------------------------------------------------
// Finalize: min across 4 chunks per pixel -> float index
// --------------------------------------------------------------------------
__global__ void finalize(float* __restrict__ out) {
    int p = blockIdx.x * 256 + threadIdx.x;
    const unsigned long long* q = &g_part[(size_t)p * 4];
    unsigned long long m = q[0];
    unsigned long long v1 = q[1], v2 = q[2], v3 = q[3];
    if (v1 < m) m = v1;
    if (v2 < m) m = v2;
    if (v3 < m) m = v3;
    out[p] = (float)(int)(unsigned)(m & 0xFFFFFFFFULL);
}

// --------------------------------------------------------------------------
// Launch
// --------------------------------------------------------------------------
extern "C" void kernel_launch(void* const* d_in, const int* in_sizes, int n_in,
                              void* d_out, int out_size) {
    const float* x    = (const float*)d_in[0];
    const float* cent = (const float*)d_in[1];
    if (n_in >= 2 && in_sizes[0] < in_sizes[1]) {
        const float* t = x; x = cent; cent = t;
    }

    cudaFuncSetAttribute(hmma_argmin,
                         cudaFuncAttributeMaxDynamicSharedMemorySize, SMEM_TOTAL);

    convert_c<<<(NK * NC + 255) / 256, 256>>>(cent);
    csq_kernel<<<NK, 128>>>(cent);
    hmma_argmin<<<NP / 128 * 4, 256, SMEM_TOTAL>>>(x);
    finalize<<<NP / 256, 256>>>((float*)d_out);
    (void)out_size;
}